// round 2
// baseline (speedup 1.0000x reference)
#include <cuda_runtime.h>
#include <cuda_fp16.h>
#include <cstdint>
#include <cstddef>

#define T_DIM 32
#define N_DIM 2048
#define F_DIM 128
#define D_DIM 128

// device scratch (no allocations allowed)
__device__ float  g_wkf[F_DIM];
__device__ float  g_c2[N_DIM];
__device__ __half g_Eh[T_DIM * N_DIM];
__device__ __half g_vh[(size_t)T_DIM * N_DIM * D_DIM];
__device__ __half g_temp[(size_t)T_DIM * N_DIM * D_DIM];

// ---------------- K1: wkf = Wk^T @ f2_w ----------------
__global__ void k1_wkf(const float* __restrict__ Wk, const float* __restrict__ f2w) {
    int f = threadIdx.x;
    float s = 0.f;
    for (int d = 0; d < F_DIM; d++) s += Wk[d * F_DIM + f] * f2w[d];
    g_wkf[f] = s;
}

// ---------------- K2: c2[n] = bk[n,:].f2_w + f2_b ----------------
__global__ void k2_c2(const float* __restrict__ bk, const float* __restrict__ f2w,
                      const float* __restrict__ f2b) {
    int n = blockIdx.x * blockDim.x + threadIdx.x;
    const float4* b4 = (const float4*)(bk + (size_t)n * F_DIM);
    const float4* w4 = (const float4*)f2w;
    float s = 0.f;
#pragma unroll
    for (int q = 0; q < F_DIM / 4; q++) {
        float4 b = b4[q], w = w4[q];
        s += b.x * w.x + b.y * w.y + b.z * w.z + b.w * w.w;
    }
    g_c2[n] = s + f2b[0];
}

// ---------------- K3: Eh = fp16(exp(f2/sqrt(D))), warp per row, 8 rows/warp ----------------
__global__ void k3_f2(const float* __restrict__ input) {
    int gwarp = (blockIdx.x * blockDim.x + threadIdx.x) >> 5;
    int lane = threadIdx.x & 31;
    float4 wk = ((const float4*)g_wkf)[lane];
#pragma unroll
    for (int rr = 0; rr < 8; rr++) {
        int row = gwarp * 8 + rr;
        float4 x = ((const float4*)(input + (size_t)row * F_DIM))[lane];
        float p = x.x * wk.x + x.y * wk.y + x.z * wk.z + x.w * wk.w;
#pragma unroll
        for (int o = 16; o; o >>= 1) p += __shfl_xor_sync(0xffffffffu, p, o);
        if (lane == 0) {
            int n = row & (N_DIM - 1);
            float f2v = (p + g_c2[n]) * (1.0f / 11.313708498984760f);
            g_Eh[row] = __float2half(expf(f2v));
        }
    }
}

// ---------------- K4: v = input @ Wv^T + bv (fp32 SGEMM, fp16 store) ----------------
// 256 threads, 64 rows/block. Thread owns d = tid&127, 32 rows (group = tid>>7).
__global__ void __launch_bounds__(256) k4_v(const float* __restrict__ input,
                                            const float* __restrict__ Wv,
                                            const float* __restrict__ bv) {
    __shared__ float Xs[64 * 8];
    __shared__ float Ws[128 * 9];
    int tid = threadIdx.x;
    int d = tid & 127, group = tid >> 7;
    size_t row0 = (size_t)blockIdx.x * 64;
    float acc[32];
#pragma unroll
    for (int r = 0; r < 32; r++) {
        size_t grow = row0 + group * 32 + r;
        acc[r] = bv[(size_t)(grow & (N_DIM - 1)) * D_DIM + d];
    }
    for (int k0 = 0; k0 < F_DIM; k0 += 8) {
        __syncthreads();
#pragma unroll
        for (int q = 0; q < 2; q++) {
            int e = tid + q * 256;
            Xs[e] = input[(row0 + (e >> 3)) * F_DIM + k0 + (e & 7)];
        }
#pragma unroll
        for (int q = 0; q < 4; q++) {
            int e = tid + q * 256;
            Ws[(e >> 3) * 9 + (e & 7)] = Wv[(size_t)(e >> 3) * F_DIM + k0 + (e & 7)];
        }
        __syncthreads();
#pragma unroll
        for (int kk = 0; kk < 8; kk++) {
            float w = Ws[d * 9 + kk];
#pragma unroll
            for (int r = 0; r < 32; r++)
                acc[r] += Xs[(group * 32 + r) * 8 + kk] * w;
        }
    }
#pragma unroll
    for (int r = 0; r < 32; r++) {
        size_t grow = row0 + group * 32 + r;
        g_vh[grow * D_DIM + d] = __float2half(acc[r]);
    }
}

// ---------------- K5: temp = (A @ v)/S via mma.sync ----------------
#define AS 72
#define BS 136

__device__ __forceinline__ void ldsm_x4(uint32_t& r0, uint32_t& r1, uint32_t& r2, uint32_t& r3, uint32_t a) {
    asm volatile("ldmatrix.sync.aligned.m8n8.x4.shared.b16 {%0,%1,%2,%3}, [%4];"
                 : "=r"(r0), "=r"(r1), "=r"(r2), "=r"(r3) : "r"(a));
}
__device__ __forceinline__ void ldsm_x4t(uint32_t& r0, uint32_t& r1, uint32_t& r2, uint32_t& r3, uint32_t a) {
    asm volatile("ldmatrix.sync.aligned.m8n8.x4.trans.shared.b16 {%0,%1,%2,%3}, [%4];"
                 : "=r"(r0), "=r"(r1), "=r"(r2), "=r"(r3) : "r"(a));
}
__device__ __forceinline__ void mma16816(float* c, uint32_t a0, uint32_t a1, uint32_t a2, uint32_t a3,
                                         uint32_t b0, uint32_t b1) {
    asm volatile("mma.sync.aligned.m16n8k16.row.col.f32.f16.f16.f32 "
                 "{%0,%1,%2,%3}, {%4,%5,%6,%7}, {%8,%9}, {%0,%1,%2,%3};"
                 : "+f"(c[0]), "+f"(c[1]), "+f"(c[2]), "+f"(c[3])
                 : "r"(a0), "r"(a1), "r"(a2), "r"(a3), "r"(b0), "r"(b1));
}

__global__ void __launch_bounds__(128) k5_attn(const int* __restrict__ adj) {
    __shared__ __half A_s[64 * AS];
    __shared__ __half B_s[64 * BS];
    __shared__ float s_part[128];
    __shared__ float s_inv[64];

    const int t  = blockIdx.x >> 5;
    const int i0 = (blockIdx.x & 31) << 6;
    const int tid = threadIdx.x;
    const int lane = tid & 31;
    const int wid = tid >> 5;

    float acc[16][4];
#pragma unroll
    for (int a = 0; a < 16; a++)
#pragma unroll
        for (int b = 0; b < 4; b++) acc[a][b] = 0.f;

    // A-build assignment: thread -> (row r, j-half hsel)
    const int r = tid >> 1;
    const int hsel = tid & 1;
    const int gi = i0 + r;
    const int* adjrow = adj + ((size_t)t * N_DIM + gi) * N_DIM;
    const __half* ehrow = g_Eh + (size_t)t * N_DIM;
    const __half* vbase = g_vh + (size_t)t * N_DIM * D_DIM;
    float s_acc = 0.f;

    uint32_t A_base = (uint32_t)__cvta_generic_to_shared(A_s);
    uint32_t B_base = (uint32_t)__cvta_generic_to_shared(B_s);
    const int p = lane & 7, g = lane >> 3;
    uint32_t a_lane = A_base + (((wid << 4) + p + ((g & 1) << 3)) * AS + ((g >> 1) << 3)) * 2;
    uint32_t b_lane = B_base + ((p + ((g & 1) << 3)) * BS + ((g >> 1) << 3)) * 2;

    for (int c = 0; c < N_DIM / 64; c++) {
        const int j0 = c * 64;
        __syncthreads();
        // stage B: v[t, j0:j0+64, :] -> B_s
        {
            const uint4* src = (const uint4*)(vbase + (size_t)j0 * D_DIM);
#pragma unroll
            for (int q = 0; q < 8; q++) {
                int e = tid + q * 128;
                int jr = e >> 4, dq = e & 15;
                uint4 w = src[jr * 16 + dq];
                *(uint4*)(&B_s[jr * BS + dq * 8]) = w;
            }
        }
        // stage A + row-sum
        {
            const int jb = j0 + hsel * 32;
            const int4* a4 = (const int4*)(adjrow + jb);
            uint4 ebuf[4];
            const uint4* e4 = (const uint4*)(ehrow + jb);
#pragma unroll
            for (int q = 0; q < 4; q++) ebuf[q] = e4[q];
            const __half* eh = (const __half*)ebuf;
            __half* arow = A_s + r * AS + hsel * 32;
#pragma unroll
            for (int q = 0; q < 8; q++) {
                int4 av = a4[q];
                int jj = jb + q * 4;
                bool m0 = (av.x != 0) | (jj + 0 == gi);
                bool m1 = (av.y != 0) | (jj + 1 == gi);
                bool m2 = (av.z != 0) | (jj + 2 == gi);
                bool m3 = (av.w != 0) | (jj + 3 == gi);
                __half z = __ushort_as_half((unsigned short)0);
                __half h0 = m0 ? eh[q * 4 + 0] : z;
                __half h1 = m1 ? eh[q * 4 + 1] : z;
                __half h2 = m2 ? eh[q * 4 + 2] : z;
                __half h3 = m3 ? eh[q * 4 + 3] : z;
                s_acc += __half2float(h0) + __half2float(h1) + __half2float(h2) + __half2float(h3);
                ((__half2*)arow)[q * 2 + 0] = __halves2half2(h0, h1);
                ((__half2*)arow)[q * 2 + 1] = __halves2half2(h2, h3);
            }
        }
        __syncthreads();
        // mma: warp wid does rows [wid*16, wid*16+16) x n=128
#pragma unroll
        for (int ks = 0; ks < 4; ks++) {
            uint32_t a0, a1, a2, a3;
            ldsm_x4(a0, a1, a2, a3, a_lane + ks * 32);
#pragma unroll
            for (int nt = 0; nt < 8; nt++) {
                uint32_t b0, b1, b2, b3;
                ldsm_x4t(b0, b1, b2, b3, b_lane + (ks * 16 * BS + nt * 16) * 2);
                mma16816(acc[2 * nt + 0], a0, a1, a2, a3, b0, b1);
                mma16816(acc[2 * nt + 1], a0, a1, a2, a3, b2, b3);
            }
        }
    }
    __syncthreads();
    s_part[r * 2 + hsel] = s_acc;
    __syncthreads();
    if (tid < 64) s_inv[tid] = 1.f / (s_part[tid * 2] + s_part[tid * 2 + 1]);
    __syncthreads();

    const int mrow = (wid << 4) + (lane >> 2);
    float inv0 = s_inv[mrow], inv1 = s_inv[mrow + 8];
    __half* out0 = g_temp + ((size_t)t * N_DIM + i0 + mrow) * D_DIM;
    __half* out1 = out0 + 8 * D_DIM;
#pragma unroll
    for (int nt = 0; nt < 16; nt++) {
        int n = nt * 8 + (lane & 3) * 2;
        *(__half2*)(out0 + n) = __floats2half2_rn(acc[nt][0] * inv0, acc[nt][1] * inv0);
        *(__half2*)(out1 + n) = __floats2half2_rn(acc[nt][2] * inv1, acc[nt][3] * inv1);
    }
}

// ---------------- K6: out = (sum_t temp) @ ffn_w^T + ffn_b ----------------
__global__ void k6_out(const float* __restrict__ ffn_w, const float* __restrict__ ffn_b,
                       float* __restrict__ out) {
    __shared__ float ts[128];
    int n = blockIdx.x, d = threadIdx.x;
    float s = 0.f;
#pragma unroll
    for (int t = 0; t < T_DIM; t++)
        s += __half2float(g_temp[((size_t)t * N_DIM + n) * D_DIM + d]);
    ts[d] = s;
    __syncthreads();
    float acc = ffn_b[d];
    const float4* w4 = (const float4*)(ffn_w + (size_t)d * D_DIM);
    const float4* t4 = (const float4*)ts;
#pragma unroll
    for (int q = 0; q < 32; q++) {
        float4 w = w4[q], x = t4[q];
        acc += w.x * x.x + w.y * x.y + w.z * x.z + w.w * x.w;
    }
    out[(size_t)n * D_DIM + d] = acc;
}

extern "C" void kernel_launch(void* const* d_in, const int* in_sizes, int n_in,
                              void* d_out, int out_size) {
    const float* input = (const float*)d_in[0];
    const int*   adj   = (const int*)d_in[1];
    const float* Wk    = (const float*)d_in[5];
    const float* bk    = (const float*)d_in[6];
    const float* Wv    = (const float*)d_in[7];
    const float* bv    = (const float*)d_in[8];
    const float* f2w   = (const float*)d_in[11];
    const float* f2b   = (const float*)d_in[12];
    const float* ffnw  = (const float*)d_in[13];
    const float* ffnb  = (const float*)d_in[14];
    float* out = (float*)d_out;

    k1_wkf<<<1, 128>>>(Wk, f2w);
    k2_c2<<<N_DIM / 256, 256>>>(bk, f2w, f2b);
    k3_f2<<<(T_DIM * N_DIM) / 64, 256>>>(input);
    k4_v<<<(T_DIM * N_DIM) / 64, 256>>>(input, Wv, bv);
    k5_attn<<<T_DIM * (N_DIM / 64), 128>>>(adj);
    k6_out<<<N_DIM, 128>>>(ffnw, ffnb, out);
}

// round 6
// speedup vs baseline: 1.2581x; 1.2581x over previous
#include <cuda_runtime.h>
#include <cuda_fp16.h>
#include <cstdint>
#include <cstddef>

#define T_DIM 32
#define N_DIM 2048
#define F_DIM 128
#define D_DIM 128

// ---------------- device scratch ----------------
__device__ float  g_wkf[F_DIM];
__device__ float  g_c2[N_DIM];
__device__ __half g_Eh[T_DIM * N_DIM];
__device__ __half g_vh[(size_t)T_DIM * N_DIM * D_DIM];   // [t][n][d]
__device__ __half g_temp[(size_t)T_DIM * N_DIM * D_DIM]; // [t][n][d]

// ---------------- mma helpers ----------------
__device__ __forceinline__ void ldsm_x4(uint32_t& r0, uint32_t& r1, uint32_t& r2, uint32_t& r3, uint32_t a) {
    asm volatile("ldmatrix.sync.aligned.m8n8.x4.shared.b16 {%0,%1,%2,%3}, [%4];"
                 : "=r"(r0), "=r"(r1), "=r"(r2), "=r"(r3) : "r"(a));
}
__device__ __forceinline__ void ldsm_x4t(uint32_t& r0, uint32_t& r1, uint32_t& r2, uint32_t& r3, uint32_t a) {
    asm volatile("ldmatrix.sync.aligned.m8n8.x4.trans.shared.b16 {%0,%1,%2,%3}, [%4];"
                 : "=r"(r0), "=r"(r1), "=r"(r2), "=r"(r3) : "r"(a));
}
__device__ __forceinline__ void mma16816(float* c, uint32_t a0, uint32_t a1, uint32_t a2, uint32_t a3,
                                         uint32_t b0, uint32_t b1) {
    asm volatile("mma.sync.aligned.m16n8k16.row.col.f32.f16.f16.f32 "
                 "{%0,%1,%2,%3}, {%4,%5,%6,%7}, {%8,%9}, {%0,%1,%2,%3};"
                 : "+f"(c[0]), "+f"(c[1]), "+f"(c[2]), "+f"(c[3])
                 : "r"(a0), "r"(a1), "r"(a2), "r"(a3), "r"(b0), "r"(b1));
}

// ---------------- K1: wkf = Wk^T @ f2_w ----------------
__global__ void k1_wkf(const float* __restrict__ Wk, const float* __restrict__ f2w) {
    int f = threadIdx.x;
    float s = 0.f;
    for (int d = 0; d < F_DIM; d++) s += Wk[d * F_DIM + f] * f2w[d];
    g_wkf[f] = s;
}

// ---------------- K2: c2[n] = bk[n,:].f2_w + f2_b ----------------
__global__ void k2_c2(const float* __restrict__ bk, const float* __restrict__ f2w,
                      const float* __restrict__ f2b) {
    int n = blockIdx.x * blockDim.x + threadIdx.x;
    const float4* b4 = (const float4*)(bk + (size_t)n * F_DIM);
    const float4* w4 = (const float4*)f2w;
    float s = 0.f;
#pragma unroll
    for (int q = 0; q < F_DIM / 4; q++) {
        float4 b = b4[q], w = w4[q];
        s += b.x * w.x + b.y * w.y + b.z * w.z + b.w * w.w;
    }
    g_c2[n] = s + f2b[0];
}

// ---------------- K3: Eh = fp16(exp(f2/sqrt(D))) ----------------
__global__ void k3_f2(const float* __restrict__ input) {
    int gwarp = (blockIdx.x * blockDim.x + threadIdx.x) >> 5;
    int lane = threadIdx.x & 31;
    float4 wk = ((const float4*)g_wkf)[lane];
#pragma unroll
    for (int rr = 0; rr < 8; rr++) {
        int row = gwarp * 8 + rr;
        float4 x = ((const float4*)(input + (size_t)row * F_DIM))[lane];
        float p = x.x * wk.x + x.y * wk.y + x.z * wk.z + x.w * wk.w;
#pragma unroll
        for (int o = 16; o; o >>= 1) p += __shfl_xor_sync(0xffffffffu, p, o);
        if (lane == 0) {
            int n = row & (N_DIM - 1);
            float f2v = (p + g_c2[n]) * (1.0f / 11.313708498984760f);
            g_Eh[row] = __float2half(expf(f2v));
        }
    }
}

// ---------------- K4: v = input @ Wv^T + bv (float4-reg compute, R2-style store) ----------------
__global__ void __launch_bounds__(256) k4_v(const float* __restrict__ input,
                                            const float* __restrict__ Wv,
                                            const float* __restrict__ bv) {
    __shared__ float Xs[64 * 8];
    __shared__ float Ws[128 * 12];
    int tid = threadIdx.x;
    int d = tid & 127, g = tid >> 7;
    size_t row0 = (size_t)blockIdx.x * 64;
    int n0 = (int)(row0 & (N_DIM - 1)) + g * 32;
    float acc[32];
#pragma unroll
    for (int r = 0; r < 32; r++) acc[r] = bv[(size_t)(n0 + r) * D_DIM + d];
    for (int k0 = 0; k0 < F_DIM; k0 += 8) {
        __syncthreads();
        if (tid < 128) {
            int rr = tid >> 1, q = tid & 1;
            *(float4*)&Xs[rr * 8 + q * 4] = *(const float4*)&input[(row0 + rr) * F_DIM + k0 + q * 4];
        }
        {
            int dd = tid >> 1, q = tid & 1;
            *(float4*)&Ws[dd * 12 + q * 4] = *(const float4*)&Wv[(size_t)dd * F_DIM + k0 + q * 4];
        }
        __syncthreads();
#pragma unroll
        for (int kq = 0; kq < 2; kq++) {
            float4 w = *(float4*)&Ws[d * 12 + kq * 4];
#pragma unroll
            for (int r = 0; r < 32; r++) {
                float4 x = *(float4*)&Xs[(g * 32 + r) * 8 + kq * 4];
                acc[r] += x.x * w.x + x.y * w.y + x.z * w.z + x.w * w.w;
            }
        }
    }
#pragma unroll
    for (int r = 0; r < 32; r++)
        g_vh[(row0 + g * 32 + r) * D_DIM + d] = __float2half(acc[r]);
}

// ---------------- K5: temp = (maskE @ v)/S  (LUT A-build, scalar S, smem normalize) ----------------
#define AS 72
#define BS 136

__global__ void __launch_bounds__(256, 2) k5_attn(const int* __restrict__ adj) {
    __shared__ __half A_s[128 * AS];
    __shared__ __half B_s[64 * BS];
    __shared__ uint2 LUT[16 * 16];
    __shared__ float s_inv[128];

    const int tid = threadIdx.x, lane = tid & 31, wid = tid >> 5;
    const int t = blockIdx.x >> 4;
    const int i0 = (blockIdx.x & 15) << 7;

    float acc[16][4];
#pragma unroll
    for (int a = 0; a < 16; a++)
#pragma unroll
        for (int b = 0; b < 4; b++) acc[a][b] = 0.f;
    float s_acc[8];
#pragma unroll
    for (int i = 0; i < 8; i++) s_acc[i] = 0.f;

    const __half* Eh_t = g_Eh + t * N_DIM;
    const __half* vh_t = g_vh + (size_t)t * N_DIM * D_DIM;
    const int* adj_base = adj + ((size_t)t * N_DIM + i0 + wid * 16 + (lane >> 4)) * N_DIM + (lane & 15) * 4;
    const int gi_row = i0 + wid * 16;

    uint32_t A_base = (uint32_t)__cvta_generic_to_shared(A_s);
    uint32_t B_base = (uint32_t)__cvta_generic_to_shared(B_s);
    const int p = lane & 7, g = lane >> 3;
    uint32_t a_lane = A_base + (((wid << 4) + p + ((g & 1) << 3)) * AS + ((g >> 1) << 3)) * 2;
    uint32_t b_lane = B_base + ((p + ((g & 1) << 3)) * BS + ((g >> 1) << 3)) * 2;

    for (int c = 0; c < N_DIM / 64; c++) {
        const int j0 = c * 64;
        __syncthreads();

        // front-batched adj loads: this lane's 8 rows x its 4-j quad
        int4 av[8];
#pragma unroll
        for (int i = 0; i < 8; i++)
            av[i] = *(const int4*)(adj_base + (size_t)(i * 2) * N_DIM + j0);

        // LUT build (per-warp redundant, identical values)
        {
            int q = lane >> 1, pb = (lane & 1) * 8;
            uint32_t e01 = *(const uint32_t*)(Eh_t + j0 + q * 4);
            uint32_t e23 = *(const uint32_t*)(Eh_t + j0 + q * 4 + 2);
#pragma unroll
            for (int pp = 0; pp < 8; pp++) {
                int pat = pb + pp;
                uint32_t mlo = ((pat & 1) ? 0x0000FFFFu : 0u) | ((pat & 2) ? 0xFFFF0000u : 0u);
                uint32_t mhi = ((pat & 4) ? 0x0000FFFFu : 0u) | ((pat & 8) ? 0xFFFF0000u : 0u);
                LUT[q * 16 + pat] = make_uint2(e01 & mlo, e23 & mhi);
            }
        }
        // B stage
#pragma unroll
        for (int q = 0; q < 4; q++) {
            int e = tid + q * 256;
            int jr = e >> 4, dq = e & 15;
            uint4 w = *(const uint4*)(vh_t + (size_t)(j0 + jr) * D_DIM + dq * 8);
            *(uint4*)(&B_s[jr * BS + dq * 8]) = w;
        }
        // A expand + scalar S accumulation from the same LUT values
        {
            int q = lane & 15;
            int jj0 = j0 + q * 4;
#pragma unroll
            for (int i = 0; i < 8; i++) {
                int r_local = i * 2 + (lane >> 4);
                int gi = gi_row + r_local;
                int4 a4 = av[i];
                unsigned nib = (a4.x != 0 ? 1u : 0u) | (a4.y != 0 ? 2u : 0u) |
                               (a4.z != 0 ? 4u : 0u) | (a4.w != 0 ? 8u : 0u);
                unsigned dd = (unsigned)(gi - jj0);
                if (dd < 4u) nib |= 1u << dd;
                uint2 v = LUT[(q << 4) + nib];
                *(uint2*)(&A_s[(wid * 16 + r_local) * AS + q * 4]) = v;
                __half2 hs = __hadd2(*(__half2*)&v.x, *(__half2*)&v.y);
                float2 fs = __half22float2(hs);
                s_acc[i] += fs.x + fs.y;
            }
        }
        __syncthreads();
        // mma
#pragma unroll
        for (int ks = 0; ks < 4; ks++) {
            uint32_t a0, a1, a2, a3;
            ldsm_x4(a0, a1, a2, a3, a_lane + ks * 32);
#pragma unroll
            for (int nt = 0; nt < 8; nt++) {
                uint32_t b0, b1, b2, b3;
                ldsm_x4t(b0, b1, b2, b3, b_lane + (ks * 16 * BS + nt * 16) * 2);
                mma16816(acc[2 * nt + 0], a0, a1, a2, a3, b0, b1);
                mma16816(acc[2 * nt + 1], a0, a1, a2, a3, b2, b3);
            }
        }
    }

    // reduce S across the 16-lane parity group (quads), write inverse to smem
#pragma unroll
    for (int i = 0; i < 8; i++) {
#pragma unroll
        for (int o = 1; o < 16; o <<= 1)
            s_acc[i] += __shfl_xor_sync(0xffffffffu, s_acc[i], o);
    }
    if ((lane & 15) == 0) {
#pragma unroll
        for (int i = 0; i < 8; i++)
            s_inv[wid * 16 + i * 2 + (lane >> 4)] = 1.0f / s_acc[i];
    }
    __syncthreads();

    const int mrow = (wid << 4) + (lane >> 2);
    float inv0 = s_inv[mrow], inv1 = s_inv[mrow + 8];
    __half* out0 = g_temp + ((size_t)t * N_DIM + i0 + mrow) * D_DIM;
    __half* out1 = out0 + 8 * D_DIM;
#pragma unroll
    for (int nt = 0; nt < 16; nt++) {
        int n = nt * 8 + (lane & 3) * 2;
        *(__half2*)(out0 + n) = __floats2half2_rn(acc[nt][0] * inv0, acc[nt][1] * inv0);
        *(__half2*)(out1 + n) = __floats2half2_rn(acc[nt][2] * inv1, acc[nt][3] * inv1);
    }
}

// ---------------- K6: out = (sum_t temp) @ ffn_w^T + ffn_b ----------------
__global__ void k6_out(const float* __restrict__ ffn_w, const float* __restrict__ ffn_b,
                       float* __restrict__ out) {
    __shared__ float ts[128];
    int n = blockIdx.x, d = threadIdx.x;
    float s = 0.f;
#pragma unroll
    for (int t = 0; t < T_DIM; t++)
        s += __half2float(g_temp[((size_t)t * N_DIM + n) * D_DIM + d]);
    ts[d] = s;
    __syncthreads();
    float acc = ffn_b[d];
    const float4* w4 = (const float4*)(ffn_w + (size_t)d * D_DIM);
    const float4* t4 = (const float4*)ts;
#pragma unroll
    for (int q = 0; q < 32; q++) {
        float4 w = w4[q], x = t4[q];
        acc += w.x * x.x + w.y * x.y + w.z * x.z + w.w * x.w;
    }
    out[(size_t)n * D_DIM + d] = acc;
}

extern "C" void kernel_launch(void* const* d_in, const int* in_sizes, int n_in,
                              void* d_out, int out_size) {
    const float* input = (const float*)d_in[0];
    const int*   adj   = (const int*)d_in[1];
    const float* Wk    = (const float*)d_in[5];
    const float* bk    = (const float*)d_in[6];
    const float* Wv    = (const float*)d_in[7];
    const float* bv    = (const float*)d_in[8];
    const float* f2w   = (const float*)d_in[11];
    const float* f2b   = (const float*)d_in[12];
    const float* ffnw  = (const float*)d_in[13];
    const float* ffnb  = (const float*)d_in[14];
    float* out = (float*)d_out;

    k1_wkf<<<1, 128>>>(Wk, f2w);
    k2_c2<<<N_DIM / 256, 256>>>(bk, f2w, f2b);
    k3_f2<<<(T_DIM * N_DIM) / 64, 256>>>(input);
    k4_v<<<(T_DIM * N_DIM) / 64, 256>>>(input, Wv, bv);
    k5_attn<<<T_DIM * (N_DIM / 128), 256>>>(adj);
    k6_out<<<N_DIM, 128>>>(ffnw, ffnb, out);
}

// round 7
// speedup vs baseline: 1.3111x; 1.0421x over previous
#include <cuda_runtime.h>
#include <cuda_fp16.h>
#include <cstdint>
#include <cstddef>

#define T_DIM 32
#define N_DIM 2048
#define F_DIM 128
#define D_DIM 128

// ---------------- device scratch ----------------
__device__ float  g_wkf[F_DIM];
__device__ float  g_c2[N_DIM];
__device__ __half g_Eh[T_DIM * N_DIM];
__device__ __half g_vh[(size_t)T_DIM * N_DIM * D_DIM];   // [t][n][d]
__device__ __half g_temp[(size_t)T_DIM * N_DIM * D_DIM]; // [t][n][d]

// ---------------- asm helpers ----------------
__device__ __forceinline__ void ldsm_x4(uint32_t& r0, uint32_t& r1, uint32_t& r2, uint32_t& r3, uint32_t a) {
    asm volatile("ldmatrix.sync.aligned.m8n8.x4.shared.b16 {%0,%1,%2,%3}, [%4];"
                 : "=r"(r0), "=r"(r1), "=r"(r2), "=r"(r3) : "r"(a));
}
__device__ __forceinline__ void ldsm_x4t(uint32_t& r0, uint32_t& r1, uint32_t& r2, uint32_t& r3, uint32_t a) {
    asm volatile("ldmatrix.sync.aligned.m8n8.x4.trans.shared.b16 {%0,%1,%2,%3}, [%4];"
                 : "=r"(r0), "=r"(r1), "=r"(r2), "=r"(r3) : "r"(a));
}
__device__ __forceinline__ void mma16816(float* c, uint32_t a0, uint32_t a1, uint32_t a2, uint32_t a3,
                                         uint32_t b0, uint32_t b1) {
    asm volatile("mma.sync.aligned.m16n8k16.row.col.f32.f16.f16.f32 "
                 "{%0,%1,%2,%3}, {%4,%5,%6,%7}, {%8,%9}, {%0,%1,%2,%3};"
                 : "+f"(c[0]), "+f"(c[1]), "+f"(c[2]), "+f"(c[3])
                 : "r"(a0), "r"(a1), "r"(a2), "r"(a3), "r"(b0), "r"(b1));
}
#define CP_ASYNC16(dst, src) asm volatile("cp.async.cg.shared.global [%0], [%1], 16;" :: "r"(dst), "l"(src) : "memory")
#define CP_COMMIT()          asm volatile("cp.async.commit_group;" ::: "memory")
#define CP_WAIT0()           asm volatile("cp.async.wait_group 0;" ::: "memory")

// ---------------- K1 ----------------
__global__ void k1_wkf(const float* __restrict__ Wk, const float* __restrict__ f2w) {
    int f = threadIdx.x;
    float s = 0.f;
    for (int d = 0; d < F_DIM; d++) s += Wk[d * F_DIM + f] * f2w[d];
    g_wkf[f] = s;
}

// ---------------- K2 ----------------
__global__ void k2_c2(const float* __restrict__ bk, const float* __restrict__ f2w,
                      const float* __restrict__ f2b) {
    int n = blockIdx.x * blockDim.x + threadIdx.x;
    const float4* b4 = (const float4*)(bk + (size_t)n * F_DIM);
    const float4* w4 = (const float4*)f2w;
    float s = 0.f;
#pragma unroll
    for (int q = 0; q < F_DIM / 4; q++) {
        float4 b = b4[q], w = w4[q];
        s += b.x * w.x + b.y * w.y + b.z * w.z + b.w * w.w;
    }
    g_c2[n] = s + f2b[0];
}

// ---------------- K3 ----------------
__global__ void k3_f2(const float* __restrict__ input) {
    int gwarp = (blockIdx.x * blockDim.x + threadIdx.x) >> 5;
    int lane = threadIdx.x & 31;
    float4 wk = ((const float4*)g_wkf)[lane];
#pragma unroll
    for (int rr = 0; rr < 8; rr++) {
        int row = gwarp * 8 + rr;
        float4 x = ((const float4*)(input + (size_t)row * F_DIM))[lane];
        float p = x.x * wk.x + x.y * wk.y + x.z * wk.z + x.w * wk.w;
#pragma unroll
        for (int o = 16; o; o >>= 1) p += __shfl_xor_sync(0xffffffffu, p, o);
        if (lane == 0) {
            int n = row & (N_DIM - 1);
            float f2v = (p + g_c2[n]) * (1.0f / 11.313708498984760f);
            g_Eh[row] = __float2half(expf(f2v));
        }
    }
}

// ---------------- K4: 8x4 register tile; fma-bound ----------------
__global__ void __launch_bounds__(256) k4_v(const float* __restrict__ input,
                                            const float* __restrict__ Wv,
                                            const float* __restrict__ bv) {
    __shared__ float Xs[64 * 8];      // [row][k]
    __shared__ float Wt[8 * 128];     // [k][d]
    int tid = threadIdx.x;
    int rg = tid >> 5, cg = tid & 31; // rows rg*8.., cols cg*4..
    size_t row0 = (size_t)blockIdx.x * 64;

    float4 acc[8];
#pragma unroll
    for (int r = 0; r < 8; r++) {
        int n = (int)((row0 + rg * 8 + r) & (N_DIM - 1));
        acc[r] = *(const float4*)&bv[(size_t)n * D_DIM + cg * 4];
    }
    for (int k0 = 0; k0 < F_DIM; k0 += 8) {
        __syncthreads();
        if (tid < 128) {
            int rr = tid >> 1, q = tid & 1;
            *(float4*)&Xs[rr * 8 + q * 4] = *(const float4*)&input[(row0 + rr) * F_DIM + k0 + q * 4];
        }
        {
            int dd = tid >> 1, q = tid & 1;
            float4 w = *(const float4*)&Wv[(size_t)dd * F_DIM + k0 + q * 4];
            Wt[(q * 4 + 0) * 128 + dd] = w.x;
            Wt[(q * 4 + 1) * 128 + dd] = w.y;
            Wt[(q * 4 + 2) * 128 + dd] = w.z;
            Wt[(q * 4 + 3) * 128 + dd] = w.w;
        }
        __syncthreads();
#pragma unroll
        for (int kq = 0; kq < 2; kq++) {
            float4 xr[8];
#pragma unroll
            for (int r = 0; r < 8; r++)
                xr[r] = *(float4*)&Xs[(rg * 8 + r) * 8 + kq * 4];
#pragma unroll
            for (int j = 0; j < 4; j++) {
                float4 w = *(float4*)&Wt[(kq * 4 + j) * 128 + cg * 4];
#pragma unroll
                for (int r = 0; r < 8; r++) {
                    float xv = (&xr[r].x)[j];
                    acc[r].x += xv * w.x; acc[r].y += xv * w.y;
                    acc[r].z += xv * w.z; acc[r].w += xv * w.w;
                }
            }
        }
    }
#pragma unroll
    for (int r = 0; r < 8; r++) {
        size_t row = row0 + rg * 8 + r;
        __half2 h01 = __floats2half2_rn(acc[r].x, acc[r].y);
        __half2 h23 = __floats2half2_rn(acc[r].z, acc[r].w);
        uint2 pk = make_uint2(*(uint32_t*)&h01, *(uint32_t*)&h23);
        *(uint2*)(g_vh + row * D_DIM + cg * 4) = pk;
    }
}

// ---------------- K5: pipelined LUT A-build + cp.async B + mma ----------------
#define AS 72
#define BS 136
#define A_BYTES (128 * AS * 2)      // 18432
#define B_BYTES (64 * BS * 2)       // 17408
#define OFF_B   (2 * A_BYTES)       // 36864
#define OFF_LUT (OFF_B + 2 * B_BYTES) // 71680
#define OFF_SI  (OFF_LUT + 2048)      // 73728
#define K5_SMEM (OFF_SI + 512)        // 74240

__global__ void __launch_bounds__(256, 2) k5_attn(const int* __restrict__ adj) {
    extern __shared__ __align__(16) char smem[];
    uint32_t sb = (uint32_t)__cvta_generic_to_shared(smem);
    uint2* LUT = (uint2*)(smem + OFF_LUT);
    float* s_inv = (float*)(smem + OFF_SI);

    const int tid = threadIdx.x, lane = tid & 31, wid = tid >> 5;
    const int t = blockIdx.x >> 4;
    const int i0 = (blockIdx.x & 15) << 7;

    float acc[16][4];
#pragma unroll
    for (int a = 0; a < 16; a++)
#pragma unroll
        for (int b = 0; b < 4; b++) acc[a][b] = 0.f;
    float s_acc[8];
#pragma unroll
    for (int i = 0; i < 8; i++) s_acc[i] = 0.f;

    const __half* Eh_t = g_Eh + t * N_DIM;
    const __half* vh_t = g_vh + (size_t)t * N_DIM * D_DIM;
    const int* adj_base = adj + ((size_t)t * N_DIM + i0 + wid * 16 + (lane >> 4)) * N_DIM + (lane & 15) * 4;
    const int gi_row = i0 + wid * 16;

    const int p = lane & 7, g = lane >> 3;
    const uint32_t a_frag = (((wid << 4) + p + ((g & 1) << 3)) * AS + ((g >> 1) << 3)) * 2;
    const uint32_t b_frag = ((p + ((g & 1) << 3)) * BS + ((g >> 1) << 3)) * 2;
    // B cp.async slice for this thread: 4 x 16B
    const int jr0 = tid >> 4, dq0 = tid & 15;   // +q*16 rows

    // prologue: B(0) via cp.async, adj(0) into regs
    {
        uint32_t bdst = sb + OFF_B;  // buf 0
#pragma unroll
        for (int q = 0; q < 4; q++) {
            int jr = jr0 + q * 16;
            CP_ASYNC16(bdst + (jr * BS + dq0 * 8) * 2, vh_t + (size_t)jr * D_DIM + dq0 * 8);
        }
        CP_COMMIT();
    }
    int4 av[8];
#pragma unroll
    for (int i = 0; i < 8; i++) av[i] = *(const int4*)(adj_base + (size_t)(i * 2) * N_DIM);

    for (int c = 0; c < N_DIM / 64; c++) {
        const int buf = c & 1;
        const int j0 = c * 64;
        const uint32_t Abase = sb + buf * A_BYTES;
        const uint32_t Bbase = sb + OFF_B + buf * B_BYTES;
        __half* A_w = (__half*)(smem + buf * A_BYTES);

        // --- build phase ---
        {   // LUT (per-warp redundant, identical values)
            int q = lane >> 1, pb = (lane & 1) * 8;
            uint32_t e01 = *(const uint32_t*)(Eh_t + j0 + q * 4);
            uint32_t e23 = *(const uint32_t*)(Eh_t + j0 + q * 4 + 2);
#pragma unroll
            for (int pp = 0; pp < 8; pp++) {
                int pat = pb + pp;
                uint32_t mlo = ((pat & 1) ? 0x0000FFFFu : 0u) | ((pat & 2) ? 0xFFFF0000u : 0u);
                uint32_t mhi = ((pat & 4) ? 0x0000FFFFu : 0u) | ((pat & 8) ? 0xFFFF0000u : 0u);
                LUT[q * 16 + pat] = make_uint2(e01 & mlo, e23 & mhi);
            }
        }
        CP_WAIT0();  // B(c) resident
        {   // A expand + scalar S
            int q = lane & 15;
            int jj0 = j0 + q * 4;
#pragma unroll
            for (int i = 0; i < 8; i++) {
                int r_local = i * 2 + (lane >> 4);
                int gi = gi_row + r_local;
                int4 a4 = av[i];
                unsigned nib = (a4.x != 0 ? 1u : 0u) | (a4.y != 0 ? 2u : 0u) |
                               (a4.z != 0 ? 4u : 0u) | (a4.w != 0 ? 8u : 0u);
                unsigned dd = (unsigned)(gi - jj0);
                if (dd < 4u) nib |= 1u << dd;
                uint2 v = LUT[(q << 4) + nib];
                *(uint2*)(&A_w[(wid * 16 + r_local) * AS + q * 4]) = v;
                __half2 hs = __hadd2(*(__half2*)&v.x, *(__half2*)&v.y);
                float2 fs = __half22float2(hs);
                s_acc[i] += fs.x + fs.y;
            }
        }
        __syncthreads();

        // --- prefetch next chunk (B via cp.async, adj via LDG) before mma ---
        if (c < N_DIM / 64 - 1) {
            const int jn = j0 + 64;
            uint32_t bdst = sb + OFF_B + (buf ^ 1) * B_BYTES;
#pragma unroll
            for (int q = 0; q < 4; q++) {
                int jr = jr0 + q * 16;
                CP_ASYNC16(bdst + (jr * BS + dq0 * 8) * 2, vh_t + (size_t)(jn + jr) * D_DIM + dq0 * 8);
            }
            CP_COMMIT();
#pragma unroll
            for (int i = 0; i < 8; i++)
                av[i] = *(const int4*)(adj_base + (size_t)(i * 2) * N_DIM + jn);
        }

        // --- mma on buf ---
        uint32_t a_lane = Abase + a_frag;
        uint32_t b_lane = Bbase + b_frag;
#pragma unroll
        for (int ks = 0; ks < 4; ks++) {
            uint32_t a0, a1, a2, a3;
            ldsm_x4(a0, a1, a2, a3, a_lane + ks * 32);
#pragma unroll
            for (int nt = 0; nt < 8; nt++) {
                uint32_t b0, b1, b2, b3;
                ldsm_x4t(b0, b1, b2, b3, b_lane + (ks * 16 * BS + nt * 16) * 2);
                mma16816(acc[2 * nt + 0], a0, a1, a2, a3, b0, b1);
                mma16816(acc[2 * nt + 1], a0, a1, a2, a3, b2, b3);
            }
        }
    }

    // S reduce across 16-lane parity groups -> smem, then normalize+store
#pragma unroll
    for (int i = 0; i < 8; i++) {
#pragma unroll
        for (int o = 1; o < 16; o <<= 1)
            s_acc[i] += __shfl_xor_sync(0xffffffffu, s_acc[i], o);
    }
    if ((lane & 15) == 0) {
#pragma unroll
        for (int i = 0; i < 8; i++)
            s_inv[wid * 16 + i * 2 + (lane >> 4)] = 1.0f / s_acc[i];
    }
    __syncthreads();

    const int mrow = (wid << 4) + (lane >> 2);
    float inv0 = s_inv[mrow], inv1 = s_inv[mrow + 8];
    __half* out0 = g_temp + ((size_t)t * N_DIM + i0 + mrow) * D_DIM;
    __half* out1 = out0 + 8 * D_DIM;
#pragma unroll
    for (int nt = 0; nt < 16; nt++) {
        int n = nt * 8 + (lane & 3) * 2;
        *(__half2*)(out0 + n) = __floats2half2_rn(acc[nt][0] * inv0, acc[nt][1] * inv0);
        *(__half2*)(out1 + n) = __floats2half2_rn(acc[nt][2] * inv1, acc[nt][3] * inv1);
    }
}

// ---------------- K6 ----------------
__global__ void k6_out(const float* __restrict__ ffn_w, const float* __restrict__ ffn_b,
                       float* __restrict__ out) {
    __shared__ float ts[128];
    int n = blockIdx.x, d = threadIdx.x;
    float s = 0.f;
#pragma unroll
    for (int t = 0; t < T_DIM; t++)
        s += __half2float(g_temp[((size_t)t * N_DIM + n) * D_DIM + d]);
    ts[d] = s;
    __syncthreads();
    float acc = ffn_b[d];
    const float4* w4 = (const float4*)(ffn_w + (size_t)d * D_DIM);
    const float4* t4 = (const float4*)ts;
#pragma unroll
    for (int q = 0; q < 32; q++) {
        float4 w = w4[q], x = t4[q];
        acc += w.x * x.x + w.y * x.y + w.z * x.z + w.w * x.w;
    }
    out[(size_t)n * D_DIM + d] = acc;
}

extern "C" void kernel_launch(void* const* d_in, const int* in_sizes, int n_in,
                              void* d_out, int out_size) {
    const float* input = (const float*)d_in[0];
    const int*   adj   = (const int*)d_in[1];
    const float* Wk    = (const float*)d_in[5];
    const float* bk    = (const float*)d_in[6];
    const float* Wv    = (const float*)d_in[7];
    const float* bv    = (const float*)d_in[8];
    const float* f2w   = (const float*)d_in[11];
    const float* f2b   = (const float*)d_in[12];
    const float* ffnw  = (const float*)d_in[13];
    const float* ffnb  = (const float*)d_in[14];
    float* out = (float*)d_out;

    static int smem_set = 0;
    if (!smem_set) {
        cudaFuncSetAttribute(k5_attn, cudaFuncAttributeMaxDynamicSharedMemorySize, K5_SMEM);
        smem_set = 1;
    }

    k1_wkf<<<1, 128>>>(Wk, f2w);
    k2_c2<<<N_DIM / 256, 256>>>(bk, f2w, f2b);
    k3_f2<<<(T_DIM * N_DIM) / 64, 256>>>(input);
    k4_v<<<(T_DIM * N_DIM) / 64, 256>>>(input, Wv, bv);
    k5_attn<<<T_DIM * (N_DIM / 128), 256, K5_SMEM>>>(adj);
    k6_out<<<N_DIM, 128>>>(ffnw, ffnb, out);
}

// round 8
// speedup vs baseline: 1.3201x; 1.0069x over previous
#include <cuda_runtime.h>
#include <cuda_fp16.h>
#include <cstdint>
#include <cstddef>

#define T_DIM 32
#define N_DIM 2048
#define F_DIM 128
#define D_DIM 128

// ---------------- device scratch ----------------
__device__ float  g_wkf[F_DIM];
__device__ float  g_c2[N_DIM];
__device__ __half g_Eh[T_DIM * N_DIM];
__device__ __half g_vT[(size_t)T_DIM * D_DIM * N_DIM];   // [t][d][n]
__device__ __half g_temp[(size_t)T_DIM * N_DIM * D_DIM]; // [t][n][d]

// ---------------- asm helpers ----------------
__device__ __forceinline__ void ldsm_x4(uint32_t& r0, uint32_t& r1, uint32_t& r2, uint32_t& r3, uint32_t a) {
    asm volatile("ldmatrix.sync.aligned.m8n8.x4.shared.b16 {%0,%1,%2,%3}, [%4];"
                 : "=r"(r0), "=r"(r1), "=r"(r2), "=r"(r3) : "r"(a));
}
__device__ __forceinline__ void mma16816(float* c, uint32_t a0, uint32_t a1, uint32_t a2, uint32_t a3,
                                         uint32_t b0, uint32_t b1) {
    asm volatile("mma.sync.aligned.m16n8k16.row.col.f32.f16.f16.f32 "
                 "{%0,%1,%2,%3}, {%4,%5,%6,%7}, {%8,%9}, {%0,%1,%2,%3};"
                 : "+f"(c[0]), "+f"(c[1]), "+f"(c[2]), "+f"(c[3])
                 : "r"(a0), "r"(a1), "r"(a2), "r"(a3), "r"(b0), "r"(b1));
}

// ---------------- K1 ----------------
__global__ void k1_wkf(const float* __restrict__ Wk, const float* __restrict__ f2w) {
    int f = threadIdx.x;
    float s = 0.f;
    for (int d = 0; d < F_DIM; d++) s += Wk[d * F_DIM + f] * f2w[d];
    g_wkf[f] = s;
}

// ---------------- K2 ----------------
__global__ void k2_c2(const float* __restrict__ bk, const float* __restrict__ f2w,
                      const float* __restrict__ f2b) {
    int n = blockIdx.x * blockDim.x + threadIdx.x;
    const float4* b4 = (const float4*)(bk + (size_t)n * F_DIM);
    const float4* w4 = (const float4*)f2w;
    float s = 0.f;
#pragma unroll
    for (int q = 0; q < F_DIM / 4; q++) {
        float4 b = b4[q], w = w4[q];
        s += b.x * w.x + b.y * w.y + b.z * w.z + b.w * w.w;
    }
    g_c2[n] = s + f2b[0];
}

// ---------------- K3 ----------------
__global__ void k3_f2(const float* __restrict__ input) {
    int gwarp = (blockIdx.x * blockDim.x + threadIdx.x) >> 5;
    int lane = threadIdx.x & 31;
    float4 wk = ((const float4*)g_wkf)[lane];
#pragma unroll
    for (int rr = 0; rr < 8; rr++) {
        int row = gwarp * 8 + rr;
        float4 x = ((const float4*)(input + (size_t)row * F_DIM))[lane];
        float p = x.x * wk.x + x.y * wk.y + x.z * wk.z + x.w * wk.w;
#pragma unroll
        for (int o = 16; o; o >>= 1) p += __shfl_xor_sync(0xffffffffu, p, o);
        if (lane == 0) {
            int n = row & (N_DIM - 1);
            float f2v = (p + g_c2[n]) * (1.0f / 11.313708498984760f);
            g_Eh[row] = __float2half(expf(f2v));
        }
    }
}

// ---------------- K4: 8x8 register tile, 128 rows x 128 d per block, writes vT ----------------
__global__ void __launch_bounds__(256) k4_v(const float* __restrict__ input,
                                            const float* __restrict__ Wv,
                                            const float* __restrict__ bv) {
    __shared__ float Xs[128 * 8];     // [row][k]
    __shared__ float Wt[8 * 128];     // [k][d]
    __shared__ __half Vs[128 * 136];  // [d][n] transpose buffer
    int tid = threadIdx.x;
    int rgi = tid >> 4, cgi = tid & 15;   // rows rgi*8.., cols cgi*8..
    size_t row0 = (size_t)blockIdx.x * 128;
    int t = (int)(row0 >> 11);
    int n0 = (int)(row0 & (N_DIM - 1));

    float4 acc[8][2];
#pragma unroll
    for (int r = 0; r < 8; r++) {
        int n = n0 + rgi * 8 + r;
        acc[r][0] = *(const float4*)&bv[(size_t)n * D_DIM + cgi * 8];
        acc[r][1] = *(const float4*)&bv[(size_t)n * D_DIM + cgi * 8 + 4];
    }
    for (int k0 = 0; k0 < F_DIM; k0 += 8) {
        __syncthreads();
        {
            int rr = tid >> 1, q = tid & 1;
            *(float4*)&Xs[rr * 8 + q * 4] = *(const float4*)&input[(row0 + rr) * F_DIM + k0 + q * 4];
        }
        {
            int dd = tid >> 1, q = tid & 1;
            float4 w = *(const float4*)&Wv[(size_t)dd * F_DIM + k0 + q * 4];
            Wt[(q * 4 + 0) * 128 + dd] = w.x;
            Wt[(q * 4 + 1) * 128 + dd] = w.y;
            Wt[(q * 4 + 2) * 128 + dd] = w.z;
            Wt[(q * 4 + 3) * 128 + dd] = w.w;
        }
        __syncthreads();
#pragma unroll
        for (int kq = 0; kq < 2; kq++) {
            float4 xr[8];
#pragma unroll
            for (int r = 0; r < 8; r++)
                xr[r] = *(float4*)&Xs[(rgi * 8 + r) * 8 + kq * 4];
#pragma unroll
            for (int j = 0; j < 4; j++) {
                float4 w0 = *(float4*)&Wt[(kq * 4 + j) * 128 + cgi * 8];
                float4 w1 = *(float4*)&Wt[(kq * 4 + j) * 128 + cgi * 8 + 4];
#pragma unroll
                for (int r = 0; r < 8; r++) {
                    float xv = (&xr[r].x)[j];
                    acc[r][0].x += xv * w0.x; acc[r][0].y += xv * w0.y;
                    acc[r][0].z += xv * w0.z; acc[r][0].w += xv * w0.w;
                    acc[r][1].x += xv * w1.x; acc[r][1].y += xv * w1.y;
                    acc[r][1].z += xv * w1.z; acc[r][1].w += xv * w1.w;
                }
            }
        }
    }
    __syncthreads();
    // transpose through smem: Vs[d][n_local]
#pragma unroll
    for (int h = 0; h < 2; h++) {
#pragma unroll
        for (int cc = 0; cc < 4; cc++) {
            int d = cgi * 8 + h * 4 + cc;
#pragma unroll
            for (int rq = 0; rq < 4; rq++) {
                float v0 = (&acc[rq * 2 + 0][h].x)[cc];
                float v1 = (&acc[rq * 2 + 1][h].x)[cc];
                *(__half2*)&Vs[d * 136 + rgi * 8 + rq * 2] = __floats2half2_rn(v0, v1);
            }
        }
    }
    __syncthreads();
#pragma unroll
    for (int q = 0; q < 8; q++) {
        int e = tid + q * 256;
        int d = e >> 4, nq = e & 15;
        *(uint4*)(g_vT + ((size_t)t * D_DIM + d) * N_DIM + n0 + nq * 8) =
            *(uint4*)&Vs[d * 136 + nq * 8];
    }
}

// ---------------- K5: LUT A-build + non-trans B from vT + mma ----------------
#define AS 72
#define BS2 72

__global__ void __launch_bounds__(256, 2) k5_attn(const int* __restrict__ adj) {
    __shared__ __half A_s[128 * AS];
    __shared__ __half B_s[128 * BS2];   // [d][j]
    __shared__ uint2 LUT[16 * 16];
    __shared__ float s_inv[128];

    const int tid = threadIdx.x, lane = tid & 31, wid = tid >> 5;
    const int t = blockIdx.x >> 4;
    const int i0 = (blockIdx.x & 15) << 7;

    float acc[16][4];
#pragma unroll
    for (int a = 0; a < 16; a++)
#pragma unroll
        for (int b = 0; b < 4; b++) acc[a][b] = 0.f;
    float s_acc[8];
#pragma unroll
    for (int i = 0; i < 8; i++) s_acc[i] = 0.f;

    const __half* Eh_t = g_Eh + t * N_DIM;
    const __half* vT_t = g_vT + (size_t)t * D_DIM * N_DIM;
    const int* adj_base = adj + ((size_t)t * N_DIM + i0 + wid * 16 + (lane >> 4)) * N_DIM + (lane & 15) * 4;
    const int gi_row = i0 + wid * 16;

    uint32_t A_base = (uint32_t)__cvta_generic_to_shared(A_s);
    uint32_t B_base = (uint32_t)__cvta_generic_to_shared(B_s);
    const int p = lane & 7, g = lane >> 3;
    // A fragment: row = wid*16 + p + ((g&1)<<3), col = ((g>>1)<<3) (+ks*16)
    uint32_t a_lane = A_base + (((wid << 4) + p + ((g & 1) << 3)) * AS + ((g >> 1) << 3)) * 2;
    // B fragment (non-trans, d-major rows): row = p + ((g>>1)<<3) (+nt*16), col = ((g&1)<<3) (+ks*16)
    uint32_t b_lane = B_base + ((p + ((g >> 1) << 3)) * BS2 + ((g & 1) << 3)) * 2;

    for (int c = 0; c < N_DIM / 64; c++) {
        const int j0 = c * 64;
        __syncthreads();

        // front-batched adj loads: this lane's 8 rows x its 4-j quad
        int4 av[8];
#pragma unroll
        for (int i = 0; i < 8; i++)
            av[i] = *(const int4*)(adj_base + (size_t)(i * 2) * N_DIM + j0);

        // LUT build (per-warp redundant, identical values)
        {
            int q = lane >> 1, pb = (lane & 1) * 8;
            uint32_t e01 = *(const uint32_t*)(Eh_t + j0 + q * 4);
            uint32_t e23 = *(const uint32_t*)(Eh_t + j0 + q * 4 + 2);
#pragma unroll
            for (int pp = 0; pp < 8; pp++) {
                int pat = pb + pp;
                uint32_t mlo = ((pat & 1) ? 0x0000FFFFu : 0u) | ((pat & 2) ? 0xFFFF0000u : 0u);
                uint32_t mhi = ((pat & 4) ? 0x0000FFFFu : 0u) | ((pat & 8) ? 0xFFFF0000u : 0u);
                LUT[q * 16 + pat] = make_uint2(e01 & mlo, e23 & mhi);
            }
        }
        // B stage: vT[t][d][j0..j0+64] -> B_s[d][j]
#pragma unroll
        for (int q = 0; q < 4; q++) {
            int e = tid + q * 256;
            int dd = e >> 3, seg = e & 7;
            uint4 w = *(const uint4*)(vT_t + (size_t)dd * N_DIM + j0 + seg * 8);
            *(uint4*)(&B_s[dd * BS2 + seg * 8]) = w;
        }
        // A expand + scalar S
        {
            int q = lane & 15;
            int jj0 = j0 + q * 4;
#pragma unroll
            for (int i = 0; i < 8; i++) {
                int r_local = i * 2 + (lane >> 4);
                int gi = gi_row + r_local;
                int4 a4 = av[i];
                unsigned nib = (a4.x != 0 ? 1u : 0u) | (a4.y != 0 ? 2u : 0u) |
                               (a4.z != 0 ? 4u : 0u) | (a4.w != 0 ? 8u : 0u);
                unsigned dd = (unsigned)(gi - jj0);
                if (dd < 4u) nib |= 1u << dd;
                uint2 v = LUT[(q << 4) + nib];
                *(uint2*)(&A_s[(wid * 16 + r_local) * AS + q * 4]) = v;
                __half2 hs = __hadd2(*(__half2*)&v.x, *(__half2*)&v.y);
                float2 fs = __half22float2(hs);
                s_acc[i] += fs.x + fs.y;
            }
        }
        __syncthreads();
        // mma: all non-trans ldmatrix
#pragma unroll
        for (int ks = 0; ks < 4; ks++) {
            uint32_t a0, a1, a2, a3;
            ldsm_x4(a0, a1, a2, a3, a_lane + ks * 32);
#pragma unroll
            for (int nt = 0; nt < 8; nt++) {
                uint32_t b0, b1, b2, b3;
                ldsm_x4(b0, b1, b2, b3, b_lane + (nt * 16 * BS2 + ks * 16) * 2);
                mma16816(acc[2 * nt + 0], a0, a1, a2, a3, b0, b1);
                mma16816(acc[2 * nt + 1], a0, a1, a2, a3, b2, b3);
            }
        }
    }

    // S reduce across 16-lane parity groups -> smem
#pragma unroll
    for (int i = 0; i < 8; i++) {
#pragma unroll
        for (int o = 1; o < 16; o <<= 1)
            s_acc[i] += __shfl_xor_sync(0xffffffffu, s_acc[i], o);
    }
    if ((lane & 15) == 0) {
#pragma unroll
        for (int i = 0; i < 8; i++)
            s_inv[wid * 16 + i * 2 + (lane >> 4)] = 1.0f / s_acc[i];
    }
    __syncthreads();

    const int mrow = (wid << 4) + (lane >> 2);
    float inv0 = s_inv[mrow], inv1 = s_inv[mrow + 8];
    __half* out0 = g_temp + ((size_t)t * N_DIM + i0 + mrow) * D_DIM;
    __half* out1 = out0 + 8 * D_DIM;
#pragma unroll
    for (int nt = 0; nt < 16; nt++) {
        int n = nt * 8 + (lane & 3) * 2;
        *(__half2*)(out0 + n) = __floats2half2_rn(acc[nt][0] * inv0, acc[nt][1] * inv0);
        *(__half2*)(out1 + n) = __floats2half2_rn(acc[nt][2] * inv1, acc[nt][3] * inv1);
    }
}

// ---------------- K6 ----------------
__global__ void k6_out(const float* __restrict__ ffn_w, const float* __restrict__ ffn_b,
                       float* __restrict__ out) {
    __shared__ float ts[128];
    int n = blockIdx.x, d = threadIdx.x;
    float s = 0.f;
#pragma unroll
    for (int t = 0; t < T_DIM; t++)
        s += __half2float(g_temp[((size_t)t * N_DIM + n) * D_DIM + d]);
    ts[d] = s;
    __syncthreads();
    float acc = ffn_b[d];
    const float4* w4 = (const float4*)(ffn_w + (size_t)d * D_DIM);
    const float4* t4 = (const float4*)ts;
#pragma unroll
    for (int q = 0; q < 32; q++) {
        float4 w = w4[q], x = t4[q];
        acc += w.x * x.x + w.y * x.y + w.z * x.z + w.w * x.w;
    }
    out[(size_t)n * D_DIM + d] = acc;
}

extern "C" void kernel_launch(void* const* d_in, const int* in_sizes, int n_in,
                              void* d_out, int out_size) {
    const float* input = (const float*)d_in[0];
    const int*   adj   = (const int*)d_in[1];
    const float* Wk    = (const float*)d_in[5];
    const float* bk    = (const float*)d_in[6];
    const float* Wv    = (const float*)d_in[7];
    const float* bv    = (const float*)d_in[8];
    const float* f2w   = (const float*)d_in[11];
    const float* f2b   = (const float*)d_in[12];
    const float* ffnw  = (const float*)d_in[13];
    const float* ffnb  = (const float*)d_in[14];
    float* out = (float*)d_out;

    k1_wkf<<<1, 128>>>(Wk, f2w);
    k2_c2<<<N_DIM / 256, 256>>>(bk, f2w, f2b);
    k3_f2<<<(T_DIM * N_DIM) / 64, 256>>>(input);
    k4_v<<<(T_DIM * N_DIM) / 128, 256>>>(input, Wv, bv);
    k5_attn<<<T_DIM * (N_DIM / 128), 256>>>(adj);
    k6_out<<<N_DIM, 128>>>(ffnw, ffnb, out);
}